// round 3
// baseline (speedup 1.0000x reference)
#include <cuda_runtime.h>
#include <cuda_bf16.h>
#include <cfloat>

#define BATCH 4
#define NPTS 4096
#define NUP 16384
#define CDIM 64
#define EPSV 1e-6f

// Scratch (no cudaMalloc allowed)
__device__ float  g_G[BATCH * NPTS * CDIM];          // projected features F@W + b
__device__ float4 g_px4[BATCH * NPTS / 4];           // SoA pos: x
__device__ float4 g_py4[BATCH * NPTS / 4];           // y
__device__ float4 g_pz4[BATCH * NPTS / 4];           // z
__device__ float4 g_pw4[BATCH * NPTS / 4];           // |p|^2

// ---------------------------------------------------------------------------
// packed f32x2 helpers
// ---------------------------------------------------------------------------
__device__ __forceinline__ unsigned long long pack2(float lo, float hi) {
    unsigned long long r;
    asm("mov.b64 %0, {%1, %2};" : "=l"(r) : "f"(lo), "f"(hi));
    return r;
}
__device__ __forceinline__ void unpack2(unsigned long long v, float& lo, float& hi) {
    asm("mov.b64 {%0, %1}, %2;" : "=f"(lo), "=f"(hi) : "l"(v));
}
__device__ __forceinline__ unsigned long long fma2(unsigned long long a,
                                                   unsigned long long b,
                                                   unsigned long long c) {
    unsigned long long d;
    asm("fma.rn.f32x2 %0, %1, %2, %3;" : "=l"(d) : "l"(a), "l"(b), "l"(c));
    return d;
}

// ---------------------------------------------------------------------------
// Fused prep (pos AoS -> SoA + |p|^2) and projection G = F@W + b.
// Blocks [0,512): proj (32 rows each).  Blocks [512,768): prep (64 pts each).
// ---------------------------------------------------------------------------
#define PROJ_ROWS 32
#define PROJ_BLOCKS (BATCH * NPTS / PROJ_ROWS)      // 512
#define PREP_BLOCKS (BATCH * NPTS / 64)             // 256

__global__ __launch_bounds__(64) void prep_proj_kernel(
    const float* __restrict__ feature,
    const float* __restrict__ pos,
    const float* __restrict__ W,
    const float* __restrict__ bias)
{
    if (blockIdx.x >= PROJ_BLOCKS) {
        int i = (blockIdx.x - PROJ_BLOCKS) * 64 + threadIdx.x;
        float x = pos[3 * i + 0];
        float y = pos[3 * i + 1];
        float z = pos[3 * i + 2];
        float n = x * x + y * y + z * z;
        ((float*)g_px4)[i] = x;
        ((float*)g_py4)[i] = y;
        ((float*)g_pz4)[i] = z;
        ((float*)g_pw4)[i] = n;
        return;
    }

    __shared__ float frow[PROJ_ROWS * CDIM];
    const int d = threadIdx.x;
    const int row0 = blockIdx.x * PROJ_ROWS;

    float wcol[CDIM];
#pragma unroll
    for (int k = 0; k < CDIM; k++) wcol[k] = __ldg(&W[k * CDIM + d]);
    const float bd = __ldg(&bias[d]);

    const float* fsrc = feature + (size_t)row0 * CDIM;
    for (int i = threadIdx.x; i < PROJ_ROWS * CDIM; i += 64)
        frow[i] = fsrc[i];
    __syncthreads();

    for (int r = 0; r < PROJ_ROWS; r++) {
        float a0 = bd, a1 = 0.f, a2 = 0.f, a3 = 0.f;
        const float* fr = &frow[r * CDIM];
#pragma unroll
        for (int k = 0; k < CDIM; k += 4) {
            a0 = fmaf(fr[k + 0], wcol[k + 0], a0);
            a1 = fmaf(fr[k + 1], wcol[k + 1], a1);
            a2 = fmaf(fr[k + 2], wcol[k + 2], a2);
            a3 = fmaf(fr[k + 3], wcol[k + 3], a3);
        }
        g_G[(size_t)(row0 + r) * CDIM + d] = (a0 + a1) + (a2 + a3);
    }
}

// ---------------------------------------------------------------------------
// 3-NN insert (rare path)
// ---------------------------------------------------------------------------
__device__ __forceinline__ void ins3(float s, int idx,
                                     float& d0, float& d1, float& d2,
                                     int& i0, int& i1, int& i2)
{
    if (s < d2) {
        if (s < d1) {
            d2 = d1; i2 = i1;
            if (s < d0) { d1 = d0; i1 = i0; d0 = s; i0 = idx; }
            else        { d1 = s;  i1 = idx; }
        } else {
            d2 = s; i2 = idx;
        }
    }
}

// ---------------------------------------------------------------------------
// Main: 32 queries/block, 4 warps = 4 candidate partitions. Each warp scans
// its quarter of the shared smem chunk (uniform LDS broadcast). Per-warp
// top-3 merged via smem (aliased onto the tile), then weighted gather of G.
// ---------------------------------------------------------------------------
#define QPB 32          // queries per block
#define SPLIT 4         // candidate partitions (warps)
#define CHUNK 2048      // candidates per smem tile (32 KB SoA)
#define WCAND (CHUNK / SPLIT)   // 512 candidates per warp per chunk

__global__ __launch_bounds__(QPB * SPLIT) void knn_apply_kernel(
    const float* __restrict__ pos_up,
    float* __restrict__ out)
{
    __shared__ float4 sx[CHUNK / 4];   // 8 KB
    __shared__ float4 sy[CHUNK / 4];
    __shared__ float4 sz[CHUNK / 4];
    __shared__ float4 sw[CHUNK / 4];

    const int lane = threadIdx.x;      // query within block
    const int wrp  = threadIdx.y;      // candidate partition
    const int tid  = wrp * QPB + lane;
    const int b = blockIdx.y;
    const int q = blockIdx.x * QPB + lane;

    const float* pu = pos_up + ((size_t)b * NUP + q) * 3;
    const float qx = pu[0], qy = pu[1], qz = pu[2];
    const unsigned long long qx2p = pack2(-2.0f * qx, -2.0f * qx);
    const unsigned long long qy2p = pack2(-2.0f * qy, -2.0f * qy);
    const unsigned long long qz2p = pack2(-2.0f * qz, -2.0f * qz);

    float d0 = FLT_MAX, d1 = FLT_MAX, d2 = FLT_MAX;
    int   i0 = 0, i1 = 0, i2 = 0;

    const int base4 = b * (NPTS / 4);

    for (int c0 = 0; c0 < NPTS; c0 += CHUNK) {
        __syncthreads();
        {
            const int t0 = base4 + c0 / 4;
            for (int i = tid; i < CHUNK / 4; i += QPB * SPLIT) {
                sx[i] = g_px4[t0 + i];
                sy[i] = g_py4[t0 + i];
                sz[i] = g_pz4[t0 + i];
                sw[i] = g_pw4[t0 + i];
            }
        }
        __syncthreads();

        const int wbase = wrp * (WCAND / 4);      // float4 offset of this warp's slice
#pragma unroll 2
        for (int j = 0; j < WCAND / 8; j++) {
            float4 X0 = sx[wbase + 2 * j], X1 = sx[wbase + 2 * j + 1];
            float4 Y0 = sy[wbase + 2 * j], Y1 = sy[wbase + 2 * j + 1];
            float4 Z0 = sz[wbase + 2 * j], Z1 = sz[wbase + 2 * j + 1];
            float4 W0 = sw[wbase + 2 * j], W1 = sw[wbase + 2 * j + 1];

            unsigned long long s01 = fma2(qx2p, pack2(X0.x, X0.y),
                                    fma2(qy2p, pack2(Y0.x, Y0.y),
                                    fma2(qz2p, pack2(Z0.x, Z0.y), pack2(W0.x, W0.y))));
            unsigned long long s23 = fma2(qx2p, pack2(X0.z, X0.w),
                                    fma2(qy2p, pack2(Y0.z, Y0.w),
                                    fma2(qz2p, pack2(Z0.z, Z0.w), pack2(W0.z, W0.w))));
            unsigned long long s45 = fma2(qx2p, pack2(X1.x, X1.y),
                                    fma2(qy2p, pack2(Y1.x, Y1.y),
                                    fma2(qz2p, pack2(Z1.x, Z1.y), pack2(W1.x, W1.y))));
            unsigned long long s67 = fma2(qx2p, pack2(X1.z, X1.w),
                                    fma2(qy2p, pack2(Y1.z, Y1.w),
                                    fma2(qz2p, pack2(Z1.z, Z1.w), pack2(W1.z, W1.w))));

            float s0, s1, s2, s3, s4, s5, s6, s7;
            unpack2(s01, s0, s1);
            unpack2(s23, s2, s3);
            unpack2(s45, s4, s5);
            unpack2(s67, s6, s7);

            float m = fminf(fminf(fminf(s0, s1), fminf(s2, s3)),
                            fminf(fminf(s4, s5), fminf(s6, s7)));

            if (m < d2) {
                const int idx = c0 + wrp * WCAND + j * 8;
                ins3(s0, idx + 0, d0, d1, d2, i0, i1, i2);
                ins3(s1, idx + 1, d0, d1, d2, i0, i1, i2);
                ins3(s2, idx + 2, d0, d1, d2, i0, i1, i2);
                ins3(s3, idx + 3, d0, d1, d2, i0, i1, i2);
                ins3(s4, idx + 4, d0, d1, d2, i0, i1, i2);
                ins3(s5, idx + 5, d0, d1, d2, i0, i1, i2);
                ins3(s6, idx + 6, d0, d1, d2, i0, i1, i2);
                ins3(s7, idx + 7, d0, d1, d2, i0, i1, i2);
            }
        }
    }

    // ---- merge across the 4 partitions (smem aliased onto the tile) ----
    float* sd   = (float*)sx;                     // [SPLIT][QPB][3]
    int*   si   = (int*)sy;                       // [SPLIT][QPB][3]
    float* swt  = (float*)sz;                     // [QPB][3] normalized weights
    int*   sidx = (int*)sw;                       // [QPB][3] final indices

    __syncthreads();   // tile reads done; safe to overwrite
    sd[(wrp * QPB + lane) * 3 + 0] = d0;
    sd[(wrp * QPB + lane) * 3 + 1] = d1;
    sd[(wrp * QPB + lane) * 3 + 2] = d2;
    si[(wrp * QPB + lane) * 3 + 0] = i0;
    si[(wrp * QPB + lane) * 3 + 1] = i1;
    si[(wrp * QPB + lane) * 3 + 2] = i2;
    __syncthreads();

    if (wrp == 0) {
        float m0 = FLT_MAX, m1 = FLT_MAX, m2 = FLT_MAX;
        int   j0 = 0, j1 = 0, j2 = 0;
#pragma unroll
        for (int p = 0; p < SPLIT; p++) {
#pragma unroll
            for (int k = 0; k < 3; k++) {
                float s  = sd[(p * QPB + lane) * 3 + k];
                int   ix = si[(p * QPB + lane) * 3 + k];
                ins3(s, ix, m0, m1, m2, j0, j1, j2);
            }
        }
        const float qn = qx * qx + qy * qy + qz * qz;
        float w0 = 1.0f / ((m0 + qn) + EPSV);
        float w1 = 1.0f / ((m1 + qn) + EPSV);
        float w2 = 1.0f / ((m2 + qn) + EPSV);
        float inv = 1.0f / (w0 + w1 + w2);
        swt[lane * 3 + 0] = w0 * inv;
        swt[lane * 3 + 1] = w1 * inv;
        swt[lane * 3 + 2] = w2 * inv;
        sidx[lane * 3 + 0] = j0;
        sidx[lane * 3 + 1] = j1;
        sidx[lane * 3 + 2] = j2;
    }
    __syncthreads();

    // ---- output: thread -> (query = tid/4, channel block = (tid%4)*16) ----
    const int oq  = tid >> 2;
    const int sub = tid & 3;
    const float wn0 = swt[oq * 3 + 0];
    const float wn1 = swt[oq * 3 + 1];
    const float wn2 = swt[oq * 3 + 2];
    const int j0 = sidx[oq * 3 + 0];
    const int j1 = sidx[oq * 3 + 1];
    const int j2 = sidx[oq * 3 + 2];

    const float4* G4 = reinterpret_cast<const float4*>(g_G);
    const float4* r0 = G4 + (size_t)(b * NPTS + j0) * (CDIM / 4) + sub * 4;
    const float4* r1 = G4 + (size_t)(b * NPTS + j1) * (CDIM / 4) + sub * 4;
    const float4* r2 = G4 + (size_t)(b * NPTS + j2) * (CDIM / 4) + sub * 4;
    const int gq = blockIdx.x * QPB + oq;
    float4* out4 = reinterpret_cast<float4*>(out)
                 + ((size_t)b * NUP + gq) * (CDIM / 4) + sub * 4;

#pragma unroll
    for (int t = 0; t < 4; t++) {
        float4 a = __ldg(&r0[t]);
        float4 c = __ldg(&r1[t]);
        float4 e = __ldg(&r2[t]);
        float4 o;
        o.x = fmaxf(0.f, fmaf(wn0, a.x, fmaf(wn1, c.x, wn2 * e.x)));
        o.y = fmaxf(0.f, fmaf(wn0, a.y, fmaf(wn1, c.y, wn2 * e.y)));
        o.z = fmaxf(0.f, fmaf(wn0, a.z, fmaf(wn1, c.z, wn2 * e.z)));
        o.w = fmaxf(0.f, fmaf(wn0, a.w, fmaf(wn1, c.w, wn2 * e.w)));
        out4[t] = o;
    }
}

// ---------------------------------------------------------------------------
extern "C" void kernel_launch(void* const* d_in, const int* in_sizes, int n_in,
                              void* d_out, int out_size)
{
    const float* feature = (const float*)d_in[0];   // (4, 4096, 64)
    const float* pos     = (const float*)d_in[1];   // (4, 4096, 3)
    const float* pos_up  = (const float*)d_in[2];   // (4, 16384, 3)
    const float* W       = (const float*)d_in[3];   // (64, 64)
    const float* bias    = (const float*)d_in[4];   // (64,)
    float* out = (float*)d_out;                     // (4, 16384, 64)

    prep_proj_kernel<<<PROJ_BLOCKS + PREP_BLOCKS, 64>>>(feature, pos, W, bias);

    dim3 grid(NUP / QPB, BATCH);
    dim3 block(QPB, SPLIT);
    knn_apply_kernel<<<grid, block>>>(pos_up, out);
}

// round 4
// speedup vs baseline: 1.1431x; 1.1431x over previous
#include <cuda_runtime.h>
#include <cuda_bf16.h>
#include <cfloat>

#define BATCH 4
#define NPTS 4096
#define NUP 16384
#define CDIM 64
#define EPSV 1e-6f

// Scratch (no cudaMalloc allowed)
__device__ float  g_G[BATCH * NPTS * CDIM];          // projected features F@W + b
__device__ ulonglong2 g_px[BATCH * NPTS / 4];        // SoA pos: x (4 floats / entry)
__device__ ulonglong2 g_py[BATCH * NPTS / 4];        // y
__device__ ulonglong2 g_pz[BATCH * NPTS / 4];        // z
__device__ ulonglong2 g_pw[BATCH * NPTS / 4];        // |p|^2

// ---------------------------------------------------------------------------
// packed f32x2 helpers
// ---------------------------------------------------------------------------
__device__ __forceinline__ unsigned long long pack2(float lo, float hi) {
    unsigned long long r;
    asm("mov.b64 %0, {%1, %2};" : "=l"(r) : "f"(lo), "f"(hi));
    return r;
}
__device__ __forceinline__ float2 unpack2(unsigned long long v) {
    float2 f;
    asm("mov.b64 {%0, %1}, %2;" : "=f"(f.x), "=f"(f.y) : "l"(v));
    return f;
}
__device__ __forceinline__ unsigned long long fma2(unsigned long long a,
                                                   unsigned long long b,
                                                   unsigned long long c) {
    unsigned long long d;
    asm("fma.rn.f32x2 %0, %1, %2, %3;" : "=l"(d) : "l"(a), "l"(b), "l"(c));
    return d;
}

// ---------------------------------------------------------------------------
// Fused prep (pos AoS -> SoA + |p|^2) and projection G = F@W + b.
// Blocks [0,512): proj (32 rows each).  Blocks [512,768): prep (64 pts each).
// ---------------------------------------------------------------------------
#define PROJ_ROWS 32
#define PROJ_BLOCKS (BATCH * NPTS / PROJ_ROWS)      // 512
#define PREP_BLOCKS (BATCH * NPTS / 64)             // 256

__global__ __launch_bounds__(64) void prep_proj_kernel(
    const float* __restrict__ feature,
    const float* __restrict__ pos,
    const float* __restrict__ W,
    const float* __restrict__ bias)
{
    if (blockIdx.x >= PROJ_BLOCKS) {
        int i = (blockIdx.x - PROJ_BLOCKS) * 64 + threadIdx.x;
        float x = pos[3 * i + 0];
        float y = pos[3 * i + 1];
        float z = pos[3 * i + 2];
        float n = x * x + y * y + z * z;
        ((float*)g_px)[i] = x;
        ((float*)g_py)[i] = y;
        ((float*)g_pz)[i] = z;
        ((float*)g_pw)[i] = n;
        return;
    }

    __shared__ float frow[PROJ_ROWS * CDIM];
    const int d = threadIdx.x;
    const int row0 = blockIdx.x * PROJ_ROWS;

    float wcol[CDIM];
#pragma unroll
    for (int k = 0; k < CDIM; k++) wcol[k] = __ldg(&W[k * CDIM + d]);
    const float bd = __ldg(&bias[d]);

    const float* fsrc = feature + (size_t)row0 * CDIM;
    for (int i = threadIdx.x; i < PROJ_ROWS * CDIM; i += 64)
        frow[i] = fsrc[i];
    __syncthreads();

    for (int r = 0; r < PROJ_ROWS; r++) {
        float a0 = bd, a1 = 0.f, a2 = 0.f, a3 = 0.f;
        const float* fr = &frow[r * CDIM];
#pragma unroll
        for (int k = 0; k < CDIM; k += 4) {
            a0 = fmaf(fr[k + 0], wcol[k + 0], a0);
            a1 = fmaf(fr[k + 1], wcol[k + 1], a1);
            a2 = fmaf(fr[k + 2], wcol[k + 2], a2);
            a3 = fmaf(fr[k + 3], wcol[k + 3], a3);
        }
        g_G[(size_t)(row0 + r) * CDIM + d] = (a0 + a1) + (a2 + a3);
    }
}

// ---------------------------------------------------------------------------
// 3-NN insert (rare path)
// ---------------------------------------------------------------------------
__device__ __forceinline__ void ins3(float s, int idx,
                                     float& d0, float& d1, float& d2,
                                     int& i0, int& i1, int& i2)
{
    if (s < d2) {
        if (s < d1) {
            d2 = d1; i2 = i1;
            if (s < d0) { d1 = d0; i1 = i0; d0 = s; i0 = idx; }
            else        { d1 = s;  i1 = idx; }
        } else {
            d2 = s; i2 = idx;
        }
    }
}

// ---------------------------------------------------------------------------
// Main: 32 queries/block x 4 partition-warps. smem tile stored as packed
// f32x2 pairs (ulonglong2) so fma.rn.f32x2 consumes LDS.128 results directly
// (no pack MOVs). CHUNK=1024 (16KB smem) + <=64 regs -> 8 blocks/SM.
// ---------------------------------------------------------------------------
#define QPB 32
#define SPLIT 4
#define CHUNK 1024
#define WCAND (CHUNK / SPLIT)    // 256 candidates per warp per chunk

__global__ __launch_bounds__(QPB * SPLIT, 8) void knn_apply_kernel(
    const float* __restrict__ pos_up,
    float* __restrict__ out)
{
    __shared__ ulonglong2 sx[CHUNK / 4];   // 4 KB each
    __shared__ ulonglong2 sy[CHUNK / 4];
    __shared__ ulonglong2 sz[CHUNK / 4];
    __shared__ ulonglong2 sw[CHUNK / 4];

    const int lane = threadIdx.x;      // query within block
    const int wrp  = threadIdx.y;      // candidate partition
    const int tid  = wrp * QPB + lane;
    const int b = blockIdx.y;
    const int q = blockIdx.x * QPB + lane;

    const float* pu = pos_up + ((size_t)b * NUP + q) * 3;
    const float qx = pu[0], qy = pu[1], qz = pu[2];
    const unsigned long long qx2p = pack2(-2.0f * qx, -2.0f * qx);
    const unsigned long long qy2p = pack2(-2.0f * qy, -2.0f * qy);
    const unsigned long long qz2p = pack2(-2.0f * qz, -2.0f * qz);

    float d0 = FLT_MAX, d1 = FLT_MAX, d2 = FLT_MAX;
    int   i0 = 0, i1 = 0, i2 = 0;

    const int base4 = b * (NPTS / 4);

    for (int c0 = 0; c0 < NPTS; c0 += CHUNK) {
        __syncthreads();
        {
            const int t0 = base4 + c0 / 4;
#pragma unroll
            for (int i = tid; i < CHUNK / 4; i += QPB * SPLIT) {
                sx[i] = g_px[t0 + i];
                sy[i] = g_py[t0 + i];
                sz[i] = g_pz[t0 + i];
                sw[i] = g_pw[t0 + i];
            }
        }
        __syncthreads();

        const int wbase = wrp * (WCAND / 4);
#pragma unroll 4
        for (int j = 0; j < WCAND / 8; j++) {
            ulonglong2 X0 = sx[wbase + 2 * j], X1 = sx[wbase + 2 * j + 1];
            ulonglong2 Y0 = sy[wbase + 2 * j], Y1 = sy[wbase + 2 * j + 1];
            ulonglong2 Z0 = sz[wbase + 2 * j], Z1 = sz[wbase + 2 * j + 1];
            ulonglong2 W0 = sw[wbase + 2 * j], W1 = sw[wbase + 2 * j + 1];

            unsigned long long s01 = fma2(qx2p, X0.x, fma2(qy2p, Y0.x, fma2(qz2p, Z0.x, W0.x)));
            unsigned long long s23 = fma2(qx2p, X0.y, fma2(qy2p, Y0.y, fma2(qz2p, Z0.y, W0.y)));
            unsigned long long s45 = fma2(qx2p, X1.x, fma2(qy2p, Y1.x, fma2(qz2p, Z1.x, W1.x)));
            unsigned long long s67 = fma2(qx2p, X1.y, fma2(qy2p, Y1.y, fma2(qz2p, Z1.y, W1.y)));

            float2 f01 = unpack2(s01);
            float2 f23 = unpack2(s23);
            float2 f45 = unpack2(s45);
            float2 f67 = unpack2(s67);

            float m = fminf(fminf(fminf(f01.x, f01.y), fminf(f23.x, f23.y)),
                            fminf(fminf(f45.x, f45.y), fminf(f67.x, f67.y)));

            if (m < d2) {
                const int idx = c0 + wrp * WCAND + j * 8;
                ins3(f01.x, idx + 0, d0, d1, d2, i0, i1, i2);
                ins3(f01.y, idx + 1, d0, d1, d2, i0, i1, i2);
                ins3(f23.x, idx + 2, d0, d1, d2, i0, i1, i2);
                ins3(f23.y, idx + 3, d0, d1, d2, i0, i1, i2);
                ins3(f45.x, idx + 4, d0, d1, d2, i0, i1, i2);
                ins3(f45.y, idx + 5, d0, d1, d2, i0, i1, i2);
                ins3(f67.x, idx + 6, d0, d1, d2, i0, i1, i2);
                ins3(f67.y, idx + 7, d0, d1, d2, i0, i1, i2);
            }
        }
    }

    // ---- merge across the 4 partitions (smem aliased onto the tile) ----
    float* sd   = (float*)sx;                     // [SPLIT*QPB][3]
    int*   si   = (int*)sy;                       // [SPLIT*QPB][3]
    float* swt  = (float*)sz;                     // [QPB][3] normalized weights
    int*   sidx = (int*)sw;                       // [QPB][3] final indices

    __syncthreads();
    sd[(wrp * QPB + lane) * 3 + 0] = d0;
    sd[(wrp * QPB + lane) * 3 + 1] = d1;
    sd[(wrp * QPB + lane) * 3 + 2] = d2;
    si[(wrp * QPB + lane) * 3 + 0] = i0;
    si[(wrp * QPB + lane) * 3 + 1] = i1;
    si[(wrp * QPB + lane) * 3 + 2] = i2;
    __syncthreads();

    if (wrp == 0) {
        float m0 = FLT_MAX, m1 = FLT_MAX, m2 = FLT_MAX;
        int   j0 = 0, j1 = 0, j2 = 0;
#pragma unroll
        for (int p = 0; p < SPLIT; p++) {
#pragma unroll
            for (int k = 0; k < 3; k++) {
                float s  = sd[(p * QPB + lane) * 3 + k];
                int   ix = si[(p * QPB + lane) * 3 + k];
                ins3(s, ix, m0, m1, m2, j0, j1, j2);
            }
        }
        const float qn = qx * qx + qy * qy + qz * qz;
        float w0 = 1.0f / ((m0 + qn) + EPSV);
        float w1 = 1.0f / ((m1 + qn) + EPSV);
        float w2 = 1.0f / ((m2 + qn) + EPSV);
        float inv = 1.0f / (w0 + w1 + w2);
        swt[lane * 3 + 0] = w0 * inv;
        swt[lane * 3 + 1] = w1 * inv;
        swt[lane * 3 + 2] = w2 * inv;
        sidx[lane * 3 + 0] = j0;
        sidx[lane * 3 + 1] = j1;
        sidx[lane * 3 + 2] = j2;
    }
    __syncthreads();

    // ---- output: thread -> (query = tid/4, channel block = (tid%4)*16) ----
    const int oq  = tid >> 2;
    const int sub = tid & 3;
    const float wn0 = swt[oq * 3 + 0];
    const float wn1 = swt[oq * 3 + 1];
    const float wn2 = swt[oq * 3 + 2];
    const int j0 = sidx[oq * 3 + 0];
    const int j1 = sidx[oq * 3 + 1];
    const int j2 = sidx[oq * 3 + 2];

    const float4* G4 = reinterpret_cast<const float4*>(g_G);
    const float4* r0 = G4 + (size_t)(b * NPTS + j0) * (CDIM / 4) + sub * 4;
    const float4* r1 = G4 + (size_t)(b * NPTS + j1) * (CDIM / 4) + sub * 4;
    const float4* r2 = G4 + (size_t)(b * NPTS + j2) * (CDIM / 4) + sub * 4;
    const int gq = blockIdx.x * QPB + oq;
    float4* out4 = reinterpret_cast<float4*>(out)
                 + ((size_t)b * NUP + gq) * (CDIM / 4) + sub * 4;

#pragma unroll
    for (int t = 0; t < 4; t++) {
        float4 a = __ldg(&r0[t]);
        float4 c = __ldg(&r1[t]);
        float4 e = __ldg(&r2[t]);
        float4 o;
        o.x = fmaxf(0.f, fmaf(wn0, a.x, fmaf(wn1, c.x, wn2 * e.x)));
        o.y = fmaxf(0.f, fmaf(wn0, a.y, fmaf(wn1, c.y, wn2 * e.y)));
        o.z = fmaxf(0.f, fmaf(wn0, a.z, fmaf(wn1, c.z, wn2 * e.z)));
        o.w = fmaxf(0.f, fmaf(wn0, a.w, fmaf(wn1, c.w, wn2 * e.w)));
        out4[t] = o;
    }
}

// ---------------------------------------------------------------------------
extern "C" void kernel_launch(void* const* d_in, const int* in_sizes, int n_in,
                              void* d_out, int out_size)
{
    const float* feature = (const float*)d_in[0];   // (4, 4096, 64)
    const float* pos     = (const float*)d_in[1];   // (4, 4096, 3)
    const float* pos_up  = (const float*)d_in[2];   // (4, 16384, 3)
    const float* W       = (const float*)d_in[3];   // (64, 64)
    const float* bias    = (const float*)d_in[4];   // (64,)
    float* out = (float*)d_out;                     // (4, 16384, 64)

    prep_proj_kernel<<<PROJ_BLOCKS + PREP_BLOCKS, 64>>>(feature, pos, W, bias);

    dim3 grid(NUP / QPB, BATCH);
    dim3 block(QPB, SPLIT);
    knn_apply_kernel<<<grid, block>>>(pos_up, out);
}